// round 10
// baseline (speedup 1.0000x reference)
#include <cuda_runtime.h>
#include <cuda_bf16.h>
#include <cstdint>

#define Bn 16
#define Cn 32
#define Tn 2048
#define Kn 129
#define SR 384            // s-range per CTA (256 outputs + 128 halo)
#define NTH 256
#define ZP 36             // z row pitch (32-bit words): bank = 4*g + tig, conflict-free
#define WP 36             // w row pitch (words)
#define QP 97             // qs pitch (floats), odd -> conflict-free diagonal gather

// ---- smem byte offsets ----
#define OFF_ZH 0
#define SZ_Z   (SR * ZP * 4)            // 55296
#define OFF_ZL (OFF_ZH + SZ_Z)          // 55296
#define OFF_WH (OFF_ZL + SZ_Z)          // 110592
#define SZ_W   (128 * WP * 4)           // 18432
#define OFF_WL (OFF_WH + SZ_W)          // 129024
#define OFF_QS (OFF_WL + SZ_W)          // 147456
#define SZ_QS  (128 * QP * 4)           // 49664
#define OFF_AF (OFF_QS + SZ_QS)         // 197120
#define OFF_BS (OFF_AF + 256)
#define OFF_WT (OFF_BS + 256)
#define SMEM_BYTES (OFF_WT + 256)       // 197888

// split v0,v1 into bf16 hi + bf16 lo pairs, packed (low half = v0)
__device__ __forceinline__ void split2(float v0, float v1, uint32_t& h, uint32_t& l) {
    __nv_bfloat162 hh = __floats2bfloat162_rn(v0, v1);
    float r0 = v0 - __bfloat162float(hh.x);
    float r1 = v1 - __bfloat162float(hh.y);
    __nv_bfloat162 ll = __floats2bfloat162_rn(r0, r1);
    h = *(uint32_t*)&hh;
    l = *(uint32_t*)&ll;
}

// m16n8k16 bf16 mma, fp32 accum (base ISA, works on .target sm_103)
__device__ __forceinline__ void mma16816(float* c, const uint32_t* a, const uint32_t* b) {
    asm volatile(
        "mma.sync.aligned.m16n8k16.row.col.f32.bf16.bf16.f32 "
        "{%0,%1,%2,%3}, {%4,%5,%6,%7}, {%8,%9}, {%0,%1,%2,%3};"
        : "+f"(c[0]), "+f"(c[1]), "+f"(c[2]), "+f"(c[3])
        : "r"(a[0]), "r"(a[1]), "r"(a[2]), "r"(a[3]), "r"(b[0]), "r"(b[1]));
}

__global__ __launch_bounds__(NTH, 1)
void wavelet_mma_kernel(
    const float* __restrict__ coeffs,     // (B,2,F,7,5,T)
    const int*   __restrict__ rows,       // (C)
    const int*   __restrict__ cols,       // (C)
    const float* __restrict__ ri_scale,   // (F)
    const float* __restrict__ ri_shift,   // (F)
    const float* __restrict__ freq_gain,  // (F)
    const float* __restrict__ synth_w,    // (C*64, 1, 129)
    float*       __restrict__ out)        // (B,C,T)
{
    extern __shared__ char smem[];
    uint32_t* zh = (uint32_t*)(smem + OFF_ZH);
    uint32_t* zl = (uint32_t*)(smem + OFF_ZL);
    uint32_t* wh = (uint32_t*)(smem + OFF_WH);
    uint32_t* wl = (uint32_t*)(smem + OFF_WL);
    float*    qs = (float*)(smem + OFF_QS);
    float*    af = (float*)(smem + OFF_AF);
    float*    bs = (float*)(smem + OFF_BS);
    float*    wt = (float*)(smem + OFF_WT);

    const int tid  = threadIdx.x;
    const int wid  = tid >> 5;
    const int lane = tid & 31;
    const int g    = lane >> 2;     // groupID (fragment row)
    const int tig  = lane & 3;      // thread-in-group

    const int bid   = blockIdx.x;
    const int chunk = bid & 7;
    const int c     = (bid >> 3) & 31;
    const int b     = bid >> 8;
    const int t0    = chunk << 8;

    const int rr = rows[c];
    const int cc = cols[c];

    // ---- per-channel constants + tail weights ----
    if (tid < 64) {
        const int f = tid & 31;
        const float gg = freq_gain[f];
        af[tid] = gg / (ri_scale[f] + 1e-12f);
        bs[tid] = ri_shift[f] * gg;
        wt[tid] = synth_w[(size_t)(c * 64 + tid) * Kn + 128];
    }
    __syncthreads();

    // ---- weights fill: w[j][i], split hi/lo ----
    {
        const int j  = tid >> 1;
        const int i0 = (tid & 1) * 32;
#pragma unroll 4
        for (int ip = 0; ip < 16; ++ip) {
            const int i = i0 + 2 * ip;
            const float w0 = synth_w[(size_t)(c * 64 + i)     * Kn + j];
            const float w1 = synth_w[(size_t)(c * 64 + i + 1) * Kn + j];
            uint32_t h, l; split2(w0, w1, h, l);
            wh[j * WP + (i >> 1)] = h;
            wl[j * WP + (i >> 1)] = l;
        }
    }

    // ---- z fill: z[s][i] = coeffs*a - b (0 outside [0,Tn)), split hi/lo ----
    const float* cb = coeffs + (size_t)(b * 64) * 71680 + (size_t)(rr * 5 + cc) * Tn;
#pragma unroll 1
    for (int s = tid; s < SR; s += NTH) {
        const int t = t0 - 64 + s;
        const bool valid = (unsigned)t < (unsigned)Tn;
#pragma unroll 8
        for (int ip = 0; ip < 32; ++ip) {
            const int i = 2 * ip;
            float v0 = valid ? fmaf(cb[(size_t)i * 71680 + t], af[i], -bs[i]) : 0.f;
            float v1 = valid ? fmaf(cb[(size_t)(i + 1) * 71680 + t], af[i + 1], -bs[i + 1]) : 0.f;
            uint32_t h, l; split2(v0, v1, h, l);
            zh[s * ZP + ip] = h;
            zl[s * ZP + ip] = l;
        }
    }
    __syncthreads();

    // ---- GEMM + gather, 4 s-chunks of 96 ----
    // warp pair (wid>>1) owns j rows [32a, 32a+32); warp parity owns 6 of 12 n-tiles
    float oacc = 0.f;
    const int jbase = (wid >> 1) * 32;
    const int nbase = (wid & 1) * 48;

#pragma unroll 1
    for (int m = 0; m < 4; ++m) {
        const int c0 = m * 96;
        float acc[2][6][4];
#pragma unroll
        for (int jt = 0; jt < 2; ++jt)
#pragma unroll
            for (int nt = 0; nt < 6; ++nt)
#pragma unroll
                for (int q = 0; q < 4; ++q) acc[jt][nt][q] = 0.f;

#pragma unroll
        for (int sp = 0; sp < 3; ++sp) {
            const uint32_t* wA = (sp == 2) ? wl : wh;
            const uint32_t* zB = (sp == 1) ? zl : zh;
#pragma unroll
            for (int ks = 0; ks < 4; ++ks) {
                const int kw = ks * 8 + tig;     // word index of k-pair
                uint32_t a[2][4];
#pragma unroll
                for (int jt = 0; jt < 2; ++jt) {
                    const int r = jbase + jt * 16 + g;
                    a[jt][0] = wA[r * WP + kw];
                    a[jt][1] = wA[(r + 8) * WP + kw];
                    a[jt][2] = wA[r * WP + kw + 4];
                    a[jt][3] = wA[(r + 8) * WP + kw + 4];
                }
#pragma unroll
                for (int nt = 0; nt < 6; ++nt) {
                    const int srow = c0 + nbase + nt * 8 + g;
                    uint32_t bb[2];
                    bb[0] = zB[srow * ZP + kw];
                    bb[1] = zB[srow * ZP + kw + 4];
                    mma16816(acc[0][nt], a[0], bb);
                    mma16816(acc[1][nt], a[1], bb);
                }
            }
        }

        // write Qt chunk to qs[j][sl]
#pragma unroll
        for (int jt = 0; jt < 2; ++jt)
#pragma unroll
            for (int nt = 0; nt < 6; ++nt) {
                const int r   = jbase + jt * 16 + g;
                const int col = nbase + nt * 8 + tig * 2;
                qs[r * QP + col]           = acc[jt][nt][0];
                qs[r * QP + col + 1]       = acc[jt][nt][1];
                qs[(r + 8) * QP + col]     = acc[jt][nt][2];
                qs[(r + 8) * QP + col + 1] = acc[jt][nt][3];
            }
        __syncthreads();

        // gather: out[u] += sum over sl of Qt[j = u+128-(c0+sl), sl]
        const int jb = tid + 128 - c0;
#pragma unroll
        for (int sl = 0; sl < 96; ++sl) {
            const int j = jb - sl;
            if ((unsigned)j < 128u) oacc += qs[j * QP + sl];
        }
        __syncthreads();
    }

    // ---- tail (j = 128): s = u, out += sum_i z[s=u][i] * w[i][128] ----
    {
        const int s = tid;
        float tail = 0.f;
#pragma unroll 8
        for (int ip = 0; ip < 32; ++ip) {
            const uint32_t hw = zh[s * ZP + ip];
            const uint32_t lw = zl[s * ZP + ip];
            const __nv_bfloat162 h2 = *(const __nv_bfloat162*)&hw;
            const __nv_bfloat162 l2 = *(const __nv_bfloat162*)&lw;
            tail += (__bfloat162float(h2.x) + __bfloat162float(l2.x)) * wt[2 * ip];
            tail += (__bfloat162float(h2.y) + __bfloat162float(l2.y)) * wt[2 * ip + 1];
        }
        out[(size_t)(b * Cn + c) * Tn + t0 + tid] = oacc + tail;
    }
}

extern "C" void kernel_launch(void* const* d_in, const int* in_sizes, int n_in,
                              void* d_out, int out_size) {
    (void)in_sizes; (void)n_in; (void)out_size;
    const float* coeffs    = (const float*)d_in[0];
    const int*   rows      = (const int*)  d_in[1];
    const int*   cols      = (const int*)  d_in[2];
    const float* ri_scale  = (const float*)d_in[3];
    const float* ri_shift  = (const float*)d_in[4];
    const float* freq_gain = (const float*)d_in[5];
    const float* synth_w   = (const float*)d_in[6];
    float* out = (float*)d_out;

    cudaFuncSetAttribute(wavelet_mma_kernel,
                         cudaFuncAttributeMaxDynamicSharedMemorySize, SMEM_BYTES);
    wavelet_mma_kernel<<<Bn * Cn * 8, NTH, SMEM_BYTES>>>(
        coeffs, rows, cols, ri_scale, ri_shift, freq_gain, synth_w, out);
}

// round 11
// speedup vs baseline: 1.2913x; 1.2913x over previous
#include <cuda_runtime.h>
#include <cuda_bf16.h>
#include <cstdint>

#define Bn 16
#define Cn 32
#define Tn 2048
#define Kn 129
#define SR 384            // s-range per CTA (256 outputs + 128 halo)
#define NTH 512
#define ZP 40             // z row pitch (words); LDS.64 conflict-free
#define WP 40             // w row pitch (words)
#define QP 97             // qs pitch (floats), odd -> conflict-free diagonal gather

// ---- smem byte offsets ----
#define OFF_ZH 0
#define SZ_Z   (SR * ZP * 4)            // 61440
#define OFF_ZL (OFF_ZH + SZ_Z)          // 61440
#define OFF_WH (OFF_ZL + SZ_Z)          // 122880
#define SZ_W   (128 * WP * 4)           // 20480
#define OFF_WL (OFF_WH + SZ_W)          // 143360
#define OFF_QS (OFF_WL + SZ_W)          // 163840
#define SZ_QS  (128 * QP * 4)           // 49664
#define OFF_AF (OFF_QS + SZ_QS)         // 213504
#define OFF_BS (OFF_AF + 256)
#define OFF_WT (OFF_BS + 256)
#define OFF_RED (OFF_WT + 256)          // 256 f32 half-sum exchange
#define SMEM_BYTES (OFF_RED + 1024)     // 215296

// split v0,v1 into bf16 hi + bf16 lo pairs, packed (low half = v0)
__device__ __forceinline__ void split2(float v0, float v1, uint32_t& h, uint32_t& l) {
    __nv_bfloat162 hh = __floats2bfloat162_rn(v0, v1);
    float r0 = v0 - __bfloat162float(hh.x);
    float r1 = v1 - __bfloat162float(hh.y);
    __nv_bfloat162 ll = __floats2bfloat162_rn(r0, r1);
    h = *(uint32_t*)&hh;
    l = *(uint32_t*)&ll;
}

// m16n8k16 bf16 mma, fp32 accum (base ISA on sm_103)
__device__ __forceinline__ void mma16816(float* c, const uint32_t* a, const uint32_t* b) {
    asm volatile(
        "mma.sync.aligned.m16n8k16.row.col.f32.bf16.bf16.f32 "
        "{%0,%1,%2,%3}, {%4,%5,%6,%7}, {%8,%9}, {%0,%1,%2,%3};"
        : "+f"(c[0]), "+f"(c[1]), "+f"(c[2]), "+f"(c[3])
        : "r"(a[0]), "r"(a[1]), "r"(a[2]), "r"(a[3]), "r"(b[0]), "r"(b[1]));
}

__global__ __launch_bounds__(NTH, 1)
void wavelet_mma_kernel(
    const float* __restrict__ coeffs,     // (B,2,F,7,5,T)
    const int*   __restrict__ rows,       // (C)
    const int*   __restrict__ cols,       // (C)
    const float* __restrict__ ri_scale,   // (F)
    const float* __restrict__ ri_shift,   // (F)
    const float* __restrict__ freq_gain,  // (F)
    const float* __restrict__ synth_w,    // (C*64, 1, 129)
    float*       __restrict__ out)        // (B,C,T)
{
    extern __shared__ char smem[];
    uint32_t* zh = (uint32_t*)(smem + OFF_ZH);
    uint32_t* zl = (uint32_t*)(smem + OFF_ZL);
    uint32_t* wh = (uint32_t*)(smem + OFF_WH);
    uint32_t* wl = (uint32_t*)(smem + OFF_WL);
    float*    qs = (float*)(smem + OFF_QS);
    float*    af = (float*)(smem + OFF_AF);
    float*    bs = (float*)(smem + OFF_BS);
    float*    wt = (float*)(smem + OFF_WT);
    float*    red = (float*)(smem + OFF_RED);

    const int tid  = threadIdx.x;
    const int wid  = tid >> 5;
    const int lane = tid & 31;
    const int g    = lane >> 2;     // fragment row (0..7)
    const int tig  = lane & 3;      // thread-in-group

    const int bid   = blockIdx.x;
    const int chunk = bid & 7;
    const int c     = (bid >> 3) & 31;
    const int b     = bid >> 8;
    const int t0    = chunk << 8;

    const int rr = rows[c];
    const int cc = cols[c];

    // ---- per-channel constants + tail weights ----
    if (tid < 64) {
        const int f = tid & 31;
        const float gg = freq_gain[f];
        af[tid] = gg / (ri_scale[f] + 1e-12f);
        bs[tid] = ri_shift[f] * gg;
        wt[tid] = synth_w[(size_t)(c * 64 + tid) * Kn + 128];
    }
    __syncthreads();

    // ---- W fill: j = tid>>2 (0..127), grp = tid&3 handles 16 channels ----
    // permuted k-word storage: within each 8-word group, orig word q -> pos
    // (q<4 ? 2q : 2(q-4)+1) so fragment pairs (q, q+4) are adjacent (LDS.64).
    {
        const int j   = tid >> 2;
        const int grp = tid & 3;
        const float* wrow = synth_w + (size_t)(c * 64) * Kn + j;
#pragma unroll
        for (int q = 0; q < 4; ++q) {
            const int c0 = grp * 16 + 2 * q;       // orig word grp*8+q
            const float w00 = wrow[(size_t)c0 * Kn];
            const float w01 = wrow[(size_t)(c0 + 1) * Kn];
            const float w10 = wrow[(size_t)(c0 + 8) * Kn];   // orig word grp*8+q+4
            const float w11 = wrow[(size_t)(c0 + 9) * Kn];
            uint32_t h0, l0, h1, l1;
            split2(w00, w01, h0, l0);
            split2(w10, w11, h1, l1);
            *(uint2*)&wh[j * WP + grp * 8 + 2 * q] = make_uint2(h0, h1);
            *(uint2*)&wl[j * WP + grp * 8 + 2 * q] = make_uint2(l0, l1);
        }
    }

    // ---- z fill: one row per thread (s = tid < 384) ----
    const float* cb = coeffs + (size_t)(b * 64) * 71680 + (size_t)(rr * 5 + cc) * Tn;
    if (tid < SR) {
        const int s = tid;
        const int t = t0 - 64 + s;
        const bool valid = (unsigned)t < (unsigned)Tn;
#pragma unroll
        for (int grp = 0; grp < 4; ++grp) {
#pragma unroll
            for (int q = 0; q < 4; ++q) {
                const int c0 = grp * 16 + 2 * q;
                float v00 = valid ? fmaf(cb[(size_t)c0 * 71680 + t], af[c0], -bs[c0]) : 0.f;
                float v01 = valid ? fmaf(cb[(size_t)(c0 + 1) * 71680 + t], af[c0 + 1], -bs[c0 + 1]) : 0.f;
                float v10 = valid ? fmaf(cb[(size_t)(c0 + 8) * 71680 + t], af[c0 + 8], -bs[c0 + 8]) : 0.f;
                float v11 = valid ? fmaf(cb[(size_t)(c0 + 9) * 71680 + t], af[c0 + 9], -bs[c0 + 9]) : 0.f;
                uint32_t h0, l0, h1, l1;
                split2(v00, v01, h0, l0);
                split2(v10, v11, h1, l1);
                *(uint2*)&zh[s * ZP + grp * 8 + 2 * q] = make_uint2(h0, h1);
                *(uint2*)&zl[s * ZP + grp * 8 + 2 * q] = make_uint2(l0, l1);
            }
        }
    }
    __syncthreads();

    // ---- GEMM + gather, 4 s-chunks of 96 ----
    // 16 warps: warp-pair (wid>>1) owns 16 j-rows; parity owns 48 of 96 s-cols
    const int jbase = (wid >> 1) * 16;
    const int nbase = (wid & 1) * 48;
    const int u  = tid & 255;          // output index (2 threads per output)
    const int hf = tid >> 8;           // half: gather s-col range
    float osum = 0.f;

#pragma unroll 1
    for (int m = 0; m < 4; ++m) {
        const int c0g = m * 96;
        float acc[6][4];
#pragma unroll
        for (int nt = 0; nt < 6; ++nt)
#pragma unroll
            for (int q = 0; q < 4; ++q) acc[nt][q] = 0.f;

#pragma unroll
        for (int sp = 0; sp < 3; ++sp) {
            const uint32_t* wA = (sp == 2) ? wl : wh;
            const uint32_t* zB = (sp == 1) ? zl : zh;
#pragma unroll
            for (int ks = 0; ks < 4; ++ks) {
                const int kwp = ks * 8 + 2 * tig;      // permuted word index
                const uint2 aLo = *(const uint2*)&wA[(jbase + g) * WP + kwp];
                const uint2 aHi = *(const uint2*)&wA[(jbase + g + 8) * WP + kwp];
                uint32_t afr[4] = {aLo.x, aHi.x, aLo.y, aHi.y};
#pragma unroll
                for (int nt = 0; nt < 6; ++nt) {
                    const int srow = c0g + nbase + nt * 8 + g;
                    const uint2 b2 = *(const uint2*)&zB[srow * ZP + kwp];
                    uint32_t bfr[2] = {b2.x, b2.y};
                    mma16816(acc[nt], afr, bfr);
                }
            }
        }

        // write Qt chunk to qs[j][sl]
#pragma unroll
        for (int nt = 0; nt < 6; ++nt) {
            const int r   = jbase + g;
            const int col = nbase + nt * 8 + tig * 2;
            qs[r * QP + col]           = acc[nt][0];
            qs[r * QP + col + 1]       = acc[nt][1];
            qs[(r + 8) * QP + col]     = acc[nt][2];
            qs[(r + 8) * QP + col + 1] = acc[nt][3];
        }
        __syncthreads();

        // gather: out[u] += sum over sl of Qt[j = u+128-(c0g+sl), sl]
        const int slb = hf * 48;
        const int jb  = u + 128 - c0g - slb;   // j at local k: jb - k
        float ga0 = 0.f, ga1 = 0.f, ga2 = 0.f, ga3 = 0.f;
#pragma unroll
        for (int k = 0; k < 48; k += 4) {
            const int j0 = jb - k;
            const int sl = slb + k;
            if ((unsigned)j0 < 128u)       ga0 += qs[j0 * QP + sl];
            if ((unsigned)(j0 - 1) < 128u) ga1 += qs[(j0 - 1) * QP + sl + 1];
            if ((unsigned)(j0 - 2) < 128u) ga2 += qs[(j0 - 2) * QP + sl + 2];
            if ((unsigned)(j0 - 3) < 128u) ga3 += qs[(j0 - 3) * QP + sl + 3];
        }
        osum += (ga0 + ga1) + (ga2 + ga3);
        __syncthreads();
    }

    // ---- combine thread-halves, add tail (j=128, s=u), write out ----
    if (hf == 1) red[u] = osum;
    __syncthreads();
    if (hf == 0) {
        float tot = osum + red[u];
        const int s = u;                // t = t0+u-64 -> local s = u
        float tail = 0.f;
#pragma unroll
        for (int grp = 0; grp < 4; ++grp) {
#pragma unroll
            for (int q = 0; q < 4; ++q) {
                const uint2 h2 = *(const uint2*)&zh[s * ZP + grp * 8 + 2 * q];
                const uint2 l2 = *(const uint2*)&zl[s * ZP + grp * 8 + 2 * q];
                const int ch = grp * 16 + 2 * q;
                const __nv_bfloat162 ha = *(const __nv_bfloat162*)&h2.x;
                const __nv_bfloat162 la = *(const __nv_bfloat162*)&l2.x;
                const __nv_bfloat162 hb2 = *(const __nv_bfloat162*)&h2.y;
                const __nv_bfloat162 lb2 = *(const __nv_bfloat162*)&l2.y;
                tail += (__bfloat162float(ha.x) + __bfloat162float(la.x)) * wt[ch];
                tail += (__bfloat162float(ha.y) + __bfloat162float(la.y)) * wt[ch + 1];
                tail += (__bfloat162float(hb2.x) + __bfloat162float(lb2.x)) * wt[ch + 8];
                tail += (__bfloat162float(hb2.y) + __bfloat162float(lb2.y)) * wt[ch + 9];
            }
        }
        out[(size_t)(b * Cn + c) * Tn + t0 + u] = tot + tail;
    }
}

extern "C" void kernel_launch(void* const* d_in, const int* in_sizes, int n_in,
                              void* d_out, int out_size) {
    (void)in_sizes; (void)n_in; (void)out_size;
    const float* coeffs    = (const float*)d_in[0];
    const int*   rows      = (const int*)  d_in[1];
    const int*   cols      = (const int*)  d_in[2];
    const float* ri_scale  = (const float*)d_in[3];
    const float* ri_shift  = (const float*)d_in[4];
    const float* freq_gain = (const float*)d_in[5];
    const float* synth_w   = (const float*)d_in[6];
    float* out = (float*)d_out;

    cudaFuncSetAttribute(wavelet_mma_kernel,
                         cudaFuncAttributeMaxDynamicSharedMemorySize, SMEM_BYTES);
    wavelet_mma_kernel<<<Bn * Cn * 8, NTH, SMEM_BYTES>>>(
        coeffs, rows, cols, ri_scale, ri_shift, freq_gain, synth_w, out);
}

// round 15
// speedup vs baseline: 1.4475x; 1.1210x over previous
#include <cuda_runtime.h>
#include <cuda_bf16.h>
#include <cstdint>

#define Bn 16
#define Cn 32
#define Tn 2048
#define Kn 129
#define SR 384            // s-range per CTA (256 outputs + 128 halo)
#define NTH 512
#define ZP 36             // z row pitch (words); pitch%32==4 -> frag LDS.64 conflict-free
#define WP 36             // w row pitch (words)
#define QT 132            // qsT row pitch (words): rows = sl (96), cols = j (128); 132%16==4

// ---- smem byte offsets ----
#define OFF_ZH 0
#define SZ_Z   (SR * ZP * 4)            // 55296
#define OFF_ZL (OFF_ZH + SZ_Z)          // 55296
#define OFF_WH (OFF_ZL + SZ_Z)          // 110592
#define SZ_W   (128 * WP * 4)           // 18432
#define OFF_WL (OFF_WH + SZ_W)          // 129024
#define OFF_QS (OFF_WL + SZ_W)          // 147456
#define SZ_QS  (96 * QT * 4)            // 50688
#define OFF_AF (OFF_QS + SZ_QS)         // 198144
#define OFF_BS (OFF_AF + 256)
#define OFF_WT (OFF_BS + 256)
#define OFF_RED (OFF_WT + 256)          // 256 f32 half-sum exchange
#define SMEM_BYTES (OFF_RED + 1024)     // 199936

// split v0,v1 into bf16 hi + bf16 lo pairs, packed (low half = v0)
__device__ __forceinline__ void split2(float v0, float v1, uint32_t& h, uint32_t& l) {
    __nv_bfloat162 hh = __floats2bfloat162_rn(v0, v1);
    float r0 = v0 - __bfloat162float(hh.x);
    float r1 = v1 - __bfloat162float(hh.y);
    __nv_bfloat162 ll = __floats2bfloat162_rn(r0, r1);
    h = *(uint32_t*)&hh;
    l = *(uint32_t*)&ll;
}

// m16n8k16 bf16 mma, fp32 accum (base ISA on sm_103)
__device__ __forceinline__ void mma16816(float* c, const uint32_t* a, const uint32_t* b) {
    asm volatile(
        "mma.sync.aligned.m16n8k16.row.col.f32.bf16.bf16.f32 "
        "{%0,%1,%2,%3}, {%4,%5,%6,%7}, {%8,%9}, {%0,%1,%2,%3};"
        : "+f"(c[0]), "+f"(c[1]), "+f"(c[2]), "+f"(c[3])
        : "r"(a[0]), "r"(a[1]), "r"(a[2]), "r"(a[3]), "r"(b[0]), "r"(b[1]));
}

__global__ __launch_bounds__(NTH, 1)
void wavelet_mma_kernel(
    const float* __restrict__ coeffs,     // (B,2,F,7,5,T)
    const int*   __restrict__ rows,       // (C)
    const int*   __restrict__ cols,       // (C)
    const float* __restrict__ ri_scale,   // (F)
    const float* __restrict__ ri_shift,   // (F)
    const float* __restrict__ freq_gain,  // (F)
    const float* __restrict__ synth_w,    // (C*64, 1, 129)
    float*       __restrict__ out)        // (B,C,T)
{
    extern __shared__ char smem[];
    uint32_t* zh = (uint32_t*)(smem + OFF_ZH);
    uint32_t* zl = (uint32_t*)(smem + OFF_ZL);
    uint32_t* wh = (uint32_t*)(smem + OFF_WH);
    uint32_t* wl = (uint32_t*)(smem + OFF_WL);
    float*    qs = (float*)(smem + OFF_QS);   // qsT[sl][j], pitch QT
    float*    af = (float*)(smem + OFF_AF);
    float*    bs = (float*)(smem + OFF_BS);
    float*    wt = (float*)(smem + OFF_WT);
    float*    red = (float*)(smem + OFF_RED);

    const int tid  = threadIdx.x;
    const int wid  = tid >> 5;
    const int lane = tid & 31;
    const int g    = lane >> 2;     // fragment row (0..7)
    const int tig  = lane & 3;      // thread-in-group

    const int bid   = blockIdx.x;
    const int chunk = bid & 7;
    const int c     = (bid >> 3) & 31;
    const int b     = bid >> 8;
    const int t0    = chunk << 8;

    const int rr = rows[c];
    const int cc = cols[c];

    // ---- per-channel constants + tail weights ----
    if (tid < 64) {
        const int f = tid & 31;
        const float gg = freq_gain[f];
        af[tid] = gg / (ri_scale[f] + 1e-12f);
        bs[tid] = ri_shift[f] * gg;
        wt[tid] = synth_w[(size_t)(c * 64 + tid) * Kn + 128];
    }
    __syncthreads();

    // ---- W fill: j = tid>>2 (0..127), grp = tid&3 handles 16 channels ----
    // permuted k-word layout: word w (0..31): grp=w>>3, p=w&7, q=p>>1, odd=p&1
    //   -> channel pair (grp*16 + 2q + 8*odd, +1)
    {
        const int j   = tid >> 2;
        const int grp = tid & 3;
        const float* wrow = synth_w + (size_t)(c * 64) * Kn + j;
#pragma unroll
        for (int q = 0; q < 4; ++q) {
            const int c0 = grp * 16 + 2 * q;
            const float w00 = wrow[(size_t)c0 * Kn];
            const float w01 = wrow[(size_t)(c0 + 1) * Kn];
            const float w10 = wrow[(size_t)(c0 + 8) * Kn];
            const float w11 = wrow[(size_t)(c0 + 9) * Kn];
            uint32_t h0, l0, h1, l1;
            split2(w00, w01, h0, l0);
            split2(w10, w11, h1, l1);
            *(uint2*)&wh[j * WP + grp * 8 + 2 * q] = make_uint2(h0, h1);
            *(uint2*)&wl[j * WP + grp * 8 + 2 * q] = make_uint2(l0, l1);
        }
    }

    // ---- z fill: one row per thread (s = tid < 384); STS.128 (conflict-free) ----
    const float* cb = coeffs + (size_t)(b * 64) * 71680 + (size_t)(rr * 5 + cc) * Tn;
    if (tid < SR) {
        const int s = tid;
        const int t = t0 - 64 + s;
        const bool valid = (unsigned)t < (unsigned)Tn;
#pragma unroll
        for (int w4 = 0; w4 < 8; ++w4) {          // 8 uint4 per row (32 words)
            uint32_t hw[4], lw[4];
#pragma unroll
            for (int e = 0; e < 4; ++e) {
                const int w   = w4 * 4 + e;
                const int grp = w >> 3, p = w & 7, q = p >> 1, odd = p & 1;
                const int ch  = grp * 16 + 2 * q + 8 * odd;
                float v0 = valid ? fmaf(cb[(size_t)ch * 71680 + t], af[ch], -bs[ch]) : 0.f;
                float v1 = valid ? fmaf(cb[(size_t)(ch + 1) * 71680 + t], af[ch + 1], -bs[ch + 1]) : 0.f;
                split2(v0, v1, hw[e], lw[e]);
            }
            *(uint4*)&zh[s * ZP + w4 * 4] = make_uint4(hw[0], hw[1], hw[2], hw[3]);
            *(uint4*)&zl[s * ZP + w4 * 4] = make_uint4(lw[0], lw[1], lw[2], lw[3]);
        }
    }
    __syncthreads();

    // ---- GEMM + gather, 4 s-chunks of 96 ----
    // 16 warps = 4 j-groups (32 rows each: 2 m16 tiles) x 4 n-groups (24 cols: 3 n8 tiles)
    const int jbase = (wid >> 2) * 32;
    const int nbase = (wid & 3) * 24;
    const int u  = tid & 255;          // output index (2 threads per output)
    const int hf = tid >> 8;           // gather half
    float osum = 0.f;

#pragma unroll 1
    for (int m = 0; m < 4; ++m) {
        const int c0g = m * 96;
        float acc[2][3][4];
#pragma unroll
        for (int jt = 0; jt < 2; ++jt)
#pragma unroll
            for (int nt = 0; nt < 3; ++nt)
#pragma unroll
                for (int q = 0; q < 4; ++q) acc[jt][nt][q] = 0.f;

#pragma unroll
        for (int ks = 0; ks < 4; ++ks) {
            const int kwp = ks * 8 + 2 * tig;
            // A fragments (h and l), cached once per k-step
            uint32_t ah[2][4], al[2][4];
#pragma unroll
            for (int jt = 0; jt < 2; ++jt) {
                const int r = jbase + jt * 16 + g;
                const uint2 hLo = *(const uint2*)&wh[r * WP + kwp];
                const uint2 hHi = *(const uint2*)&wh[(r + 8) * WP + kwp];
                const uint2 lLo = *(const uint2*)&wl[r * WP + kwp];
                const uint2 lHi = *(const uint2*)&wl[(r + 8) * WP + kwp];
                ah[jt][0] = hLo.x; ah[jt][1] = hHi.x; ah[jt][2] = hLo.y; ah[jt][3] = hHi.y;
                al[jt][0] = lLo.x; al[jt][1] = lHi.x; al[jt][2] = lLo.y; al[jt][3] = lHi.y;
            }
            // B fragments (h and l), cached once per k-step
            uint32_t bh[3][2], bl[3][2];
#pragma unroll
            for (int nt = 0; nt < 3; ++nt) {
                const int srow = c0g + nbase + nt * 8 + g;
                const uint2 h2 = *(const uint2*)&zh[srow * ZP + kwp];
                const uint2 l2 = *(const uint2*)&zl[srow * ZP + kwp];
                bh[nt][0] = h2.x; bh[nt][1] = h2.y;
                bl[nt][0] = l2.x; bl[nt][1] = l2.y;
            }
            // 3-split MMAs from cached fragments
#pragma unroll
            for (int jt = 0; jt < 2; ++jt)
#pragma unroll
                for (int nt = 0; nt < 3; ++nt) {
                    mma16816(acc[jt][nt], ah[jt], bh[nt]);
                    mma16816(acc[jt][nt], ah[jt], bl[nt]);
                    mma16816(acc[jt][nt], al[jt], bh[nt]);
                }
        }

        // store transposed: qsT[sl][j]  (STS.32, banks 8*tig+g: conflict-free)
#pragma unroll
        for (int jt = 0; jt < 2; ++jt)
#pragma unroll
            for (int nt = 0; nt < 3; ++nt) {
                const int r   = jbase + jt * 16 + g;
                const int col = nbase + nt * 8 + 2 * tig;
                qs[col * QT + r]           = acc[jt][nt][0];
                qs[(col + 1) * QT + r]     = acc[jt][nt][1];
                qs[col * QT + r + 8]       = acc[jt][nt][2];
                qs[(col + 1) * QT + r + 8] = acc[jt][nt][3];
            }
        __syncthreads();

        // gather: out[u] += sum over sl of Qt[j = u+128-(c0g+sl), sl]
        const int slb = hf * 48;
        const int jb  = u + 128 - c0g - slb;   // j at local k: jb - k
        float ga0 = 0.f, ga1 = 0.f, ga2 = 0.f, ga3 = 0.f;
#pragma unroll
        for (int k = 0; k < 48; k += 4) {
            const int j0 = jb - k;
            const int sl = slb + k;
            if ((unsigned)j0 < 128u)       ga0 += qs[sl * QT + j0];
            if ((unsigned)(j0 - 1) < 128u) ga1 += qs[(sl + 1) * QT + j0 - 1];
            if ((unsigned)(j0 - 2) < 128u) ga2 += qs[(sl + 2) * QT + j0 - 2];
            if ((unsigned)(j0 - 3) < 128u) ga3 += qs[(sl + 3) * QT + j0 - 3];
        }
        osum += (ga0 + ga1) + (ga2 + ga3);
        __syncthreads();
    }

    // ---- combine thread-halves, add tail (j=128, s=u), write out ----
    if (hf == 1) red[u] = osum;
    __syncthreads();
    if (hf == 0) {
        float tot = osum + red[u];
        const int s = u;                // t = t0+u-64+128 -> local s = u
        float tail = 0.f;
#pragma unroll
        for (int grp = 0; grp < 4; ++grp) {
#pragma unroll
            for (int q = 0; q < 4; ++q) {
                const uint2 h2 = *(const uint2*)&zh[s * ZP + grp * 8 + 2 * q];
                const uint2 l2 = *(const uint2*)&zl[s * ZP + grp * 8 + 2 * q];
                const int ch = grp * 16 + 2 * q;
                const __nv_bfloat162 ha = *(const __nv_bfloat162*)&h2.x;
                const __nv_bfloat162 la = *(const __nv_bfloat162*)&l2.x;
                const __nv_bfloat162 hb2 = *(const __nv_bfloat162*)&h2.y;
                const __nv_bfloat162 lb2 = *(const __nv_bfloat162*)&l2.y;
                tail += (__bfloat162float(ha.x) + __bfloat162float(la.x)) * wt[ch];
                tail += (__bfloat162float(ha.y) + __bfloat162float(la.y)) * wt[ch + 1];
                tail += (__bfloat162float(hb2.x) + __bfloat162float(lb2.x)) * wt[ch + 8];
                tail += (__bfloat162float(hb2.y) + __bfloat162float(lb2.y)) * wt[ch + 9];
            }
        }
        out[(size_t)(b * Cn + c) * Tn + t0 + u] = tot + tail;
    }
}

extern "C" void kernel_launch(void* const* d_in, const int* in_sizes, int n_in,
                              void* d_out, int out_size) {
    (void)in_sizes; (void)n_in; (void)out_size;
    const float* coeffs    = (const float*)d_in[0];
    const int*   rows      = (const int*)  d_in[1];
    const int*   cols      = (const int*)  d_in[2];
    const float* ri_scale  = (const float*)d_in[3];
    const float* ri_shift  = (const float*)d_in[4];
    const float* freq_gain = (const float*)d_in[5];
    const float* synth_w   = (const float*)d_in[6];
    float* out = (float*)d_out;

    cudaFuncSetAttribute(wavelet_mma_kernel,
                         cudaFuncAttributeMaxDynamicSharedMemorySize, SMEM_BYTES);
    wavelet_mma_kernel<<<Bn * Cn * 8, NTH, SMEM_BYTES>>>(
        coeffs, rows, cols, ri_scale, ri_shift, freq_gain, synth_w, out);
}

// round 16
// speedup vs baseline: 1.6810x; 1.1613x over previous
#include <cuda_runtime.h>
#include <cuda_bf16.h>
#include <cstdint>

#define Bn 16
#define Cn 32
#define Tn 2048
#define Kn 129
#define SR 384            // s-range per CTA (256 outputs + 128 halo)
#define NTH 512
#define ZP 36             // pitch%32==4: LDS.32 frag loads (4g+tig) conflict-free
#define WP 36
#define QT 132            // qsT pitch: stores banks 8tig+g, gather consecutive -> CF

// ---- smem byte offsets ----
#define OFF_ZH 0
#define SZ_Z   (SR * ZP * 4)            // 55296
#define OFF_ZL (OFF_ZH + SZ_Z)          // 55296
#define OFF_WH (OFF_ZL + SZ_Z)          // 110592
#define SZ_W   (128 * WP * 4)           // 18432
#define OFF_WL (OFF_WH + SZ_W)          // 129024
#define OFF_QS (OFF_WL + SZ_W)          // 147456
#define SZ_QS  (96 * QT * 4)            // 50688
#define OFF_AF (OFF_QS + SZ_QS)         // 198144
#define OFF_BS (OFF_AF + 256)
#define OFF_WT (OFF_BS + 256)
#define OFF_RED (OFF_WT + 256)          // 256 f32 half-sum exchange
#define SMEM_BYTES (OFF_RED + 1024)     // 199936

// split v0,v1 into bf16 hi + bf16 lo pairs, packed (low half = v0)
__device__ __forceinline__ void split2(float v0, float v1, uint32_t& h, uint32_t& l) {
    __nv_bfloat162 hh = __floats2bfloat162_rn(v0, v1);
    float r0 = v0 - __bfloat162float(hh.x);
    float r1 = v1 - __bfloat162float(hh.y);
    __nv_bfloat162 ll = __floats2bfloat162_rn(r0, r1);
    h = *(uint32_t*)&hh;
    l = *(uint32_t*)&ll;
}

// m16n8k16 bf16 mma, fp32 accum (base ISA on sm_103)
__device__ __forceinline__ void mma16816(float* c, const uint32_t* a, const uint32_t* b) {
    asm volatile(
        "mma.sync.aligned.m16n8k16.row.col.f32.bf16.bf16.f32 "
        "{%0,%1,%2,%3}, {%4,%5,%6,%7}, {%8,%9}, {%0,%1,%2,%3};"
        : "+f"(c[0]), "+f"(c[1]), "+f"(c[2]), "+f"(c[3])
        : "r"(a[0]), "r"(a[1]), "r"(a[2]), "r"(a[3]), "r"(b[0]), "r"(b[1]));
}

__global__ __launch_bounds__(NTH, 1)
void wavelet_mma_kernel(
    const float* __restrict__ coeffs,     // (B,2,F,7,5,T)
    const int*   __restrict__ rows,       // (C)
    const int*   __restrict__ cols,       // (C)
    const float* __restrict__ ri_scale,   // (F)
    const float* __restrict__ ri_shift,   // (F)
    const float* __restrict__ freq_gain,  // (F)
    const float* __restrict__ synth_w,    // (C*64, 1, 129)
    float*       __restrict__ out)        // (B,C,T)
{
    extern __shared__ char smem[];
    uint32_t* zh = (uint32_t*)(smem + OFF_ZH);
    uint32_t* zl = (uint32_t*)(smem + OFF_ZL);
    uint32_t* wh = (uint32_t*)(smem + OFF_WH);
    uint32_t* wl = (uint32_t*)(smem + OFF_WL);
    float*    qs = (float*)(smem + OFF_QS);   // qsT[sl][j], pitch QT
    float*    af = (float*)(smem + OFF_AF);
    float*    bs = (float*)(smem + OFF_BS);
    float*    wt = (float*)(smem + OFF_WT);
    float*    red = (float*)(smem + OFF_RED);

    const int tid  = threadIdx.x;
    const int wid  = tid >> 5;
    const int lane = tid & 31;
    const int g    = lane >> 2;     // fragment row (0..7)
    const int tig  = lane & 3;      // thread-in-group

    const int bid   = blockIdx.x;
    const int chunk = bid & 7;
    const int c     = (bid >> 3) & 31;
    const int b     = bid >> 8;
    const int t0    = chunk << 8;

    const int rr = rows[c];
    const int cc = cols[c];

    // ---- per-channel constants + tail weights ----
    if (tid < 64) {
        const int f = tid & 31;
        const float gg = freq_gain[f];
        af[tid] = gg / (ri_scale[f] + 1e-12f);
        bs[tid] = ri_shift[f] * gg;
        wt[tid] = synth_w[(size_t)(c * 64 + tid) * Kn + 128];
    }
    __syncthreads();

    // ---- W fill: plain layout, word w <-> channel pair (2w, 2w+1) ----
    {
        const int j   = tid >> 2;
        const int grp = tid & 3;
        const float* wrow = synth_w + (size_t)(c * 64) * Kn + j;
#pragma unroll
        for (int q = 0; q < 8; ++q) {
            const int w  = grp * 8 + q;
            const int ch = 2 * w;
            const float w0 = wrow[(size_t)ch * Kn];
            const float w1 = wrow[(size_t)(ch + 1) * Kn];
            uint32_t h, l;
            split2(w0, w1, h, l);
            wh[j * WP + w] = h;
            wl[j * WP + w] = l;
        }
    }

    // ---- z fill: one row per thread; plain layout; STS.128 (conflict-free) ----
    const float* cb = coeffs + (size_t)(b * 64) * 71680 + (size_t)(rr * 5 + cc) * Tn;
    if (tid < SR) {
        const int s = tid;
        const int t = t0 - 64 + s;
        const bool valid = (unsigned)t < (unsigned)Tn;
#pragma unroll
        for (int w4 = 0; w4 < 8; ++w4) {          // 8 uint4 per row (32 words)
            uint32_t hw[4], lw[4];
#pragma unroll
            for (int e = 0; e < 4; ++e) {
                const int w  = w4 * 4 + e;
                const int ch = 2 * w;
                float v0 = valid ? fmaf(cb[(size_t)ch * 71680 + t], af[ch], -bs[ch]) : 0.f;
                float v1 = valid ? fmaf(cb[(size_t)(ch + 1) * 71680 + t], af[ch + 1], -bs[ch + 1]) : 0.f;
                split2(v0, v1, hw[e], lw[e]);
            }
            *(uint4*)&zh[s * ZP + w4 * 4] = make_uint4(hw[0], hw[1], hw[2], hw[3]);
            *(uint4*)&zl[s * ZP + w4 * 4] = make_uint4(lw[0], lw[1], lw[2], lw[3]);
        }
    }
    __syncthreads();

    // ---- GEMM + gather, 4 s-chunks of 96 ----
    // 16 warps = 4 j-groups (2 m16 tiles) x 4 n-groups (3 n8 tiles)
    const int jbase = (wid >> 2) * 32;
    const int nbase = (wid & 3) * 24;
    const int u  = tid & 255;          // output index (2 threads per output)
    const int hf = tid >> 8;           // gather half
    float osum = 0.f;

#pragma unroll 1
    for (int m = 0; m < 4; ++m) {
        const int c0g = m * 96;
        float acc[2][3][4];
#pragma unroll
        for (int jt = 0; jt < 2; ++jt)
#pragma unroll
            for (int nt = 0; nt < 3; ++nt)
#pragma unroll
                for (int q = 0; q < 4; ++q) acc[jt][nt][q] = 0.f;

#pragma unroll
        for (int ks = 0; ks < 4; ++ks) {
            const int kw = ks * 8 + tig;          // R8-verified LDS.32 mapping
            // A fragments (h and l), cached once per k-step (scalar LDS.32, CF)
            uint32_t ah[2][4], al[2][4];
#pragma unroll
            for (int jt = 0; jt < 2; ++jt) {
                const int r = jbase + jt * 16 + g;
                ah[jt][0] = wh[r * WP + kw];
                ah[jt][1] = wh[(r + 8) * WP + kw];
                ah[jt][2] = wh[r * WP + kw + 4];
                ah[jt][3] = wh[(r + 8) * WP + kw + 4];
                al[jt][0] = wl[r * WP + kw];
                al[jt][1] = wl[(r + 8) * WP + kw];
                al[jt][2] = wl[r * WP + kw + 4];
                al[jt][3] = wl[(r + 8) * WP + kw + 4];
            }
            // B fragments (h and l), cached once per k-step
            uint32_t bh[3][2], bl[3][2];
#pragma unroll
            for (int nt = 0; nt < 3; ++nt) {
                const int srow = c0g + nbase + nt * 8 + g;
                bh[nt][0] = zh[srow * ZP + kw];
                bh[nt][1] = zh[srow * ZP + kw + 4];
                bl[nt][0] = zl[srow * ZP + kw];
                bl[nt][1] = zl[srow * ZP + kw + 4];
            }
            // 3-split MMAs from cached fragments
#pragma unroll
            for (int jt = 0; jt < 2; ++jt)
#pragma unroll
                for (int nt = 0; nt < 3; ++nt) {
                    mma16816(acc[jt][nt], ah[jt], bh[nt]);
                    mma16816(acc[jt][nt], ah[jt], bl[nt]);
                    mma16816(acc[jt][nt], al[jt], bh[nt]);
                }
        }

        // store transposed: qsT[sl][j]  (STS.32, banks 8tig+g: conflict-free)
#pragma unroll
        for (int jt = 0; jt < 2; ++jt)
#pragma unroll
            for (int nt = 0; nt < 3; ++nt) {
                const int r   = jbase + jt * 16 + g;
                const int col = nbase + nt * 8 + 2 * tig;
                qs[col * QT + r]           = acc[jt][nt][0];
                qs[(col + 1) * QT + r]     = acc[jt][nt][1];
                qs[col * QT + r + 8]       = acc[jt][nt][2];
                qs[(col + 1) * QT + r + 8] = acc[jt][nt][3];
            }
        __syncthreads();

        // gather: out[u] += sum over sl of Qt[j = u+128-(c0g+sl), sl]
        const int slb = hf * 48;
        const int jb  = u + 128 - c0g - slb;   // j at local k: jb - k
        float ga0 = 0.f, ga1 = 0.f, ga2 = 0.f, ga3 = 0.f;
#pragma unroll
        for (int k = 0; k < 48; k += 4) {
            const int j0 = jb - k;
            const int sl = slb + k;
            if ((unsigned)j0 < 128u)       ga0 += qs[sl * QT + j0];
            if ((unsigned)(j0 - 1) < 128u) ga1 += qs[(sl + 1) * QT + j0 - 1];
            if ((unsigned)(j0 - 2) < 128u) ga2 += qs[(sl + 2) * QT + j0 - 2];
            if ((unsigned)(j0 - 3) < 128u) ga3 += qs[(sl + 3) * QT + j0 - 3];
        }
        osum += (ga0 + ga1) + (ga2 + ga3);
        __syncthreads();
    }

    // ---- combine thread-halves, add tail (j=128, s=u), write out ----
    if (hf == 1) red[u] = osum;
    __syncthreads();
    if (hf == 0) {
        float tot = osum + red[u];
        const int s = u;                // local s = u for the j=128 tap
        float tail = 0.f;
#pragma unroll
        for (int w4 = 0; w4 < 8; ++w4) {
            const uint4 h4 = *(const uint4*)&zh[s * ZP + w4 * 4];
            const uint4 l4 = *(const uint4*)&zl[s * ZP + w4 * 4];
            const uint32_t hws[4] = {h4.x, h4.y, h4.z, h4.w};
            const uint32_t lws[4] = {l4.x, l4.y, l4.z, l4.w};
#pragma unroll
            for (int e = 0; e < 4; ++e) {
                const int ch = 2 * (w4 * 4 + e);
                const __nv_bfloat162 h2 = *(const __nv_bfloat162*)&hws[e];
                const __nv_bfloat162 l2 = *(const __nv_bfloat162*)&lws[e];
                tail += (__bfloat162float(h2.x) + __bfloat162float(l2.x)) * wt[ch];
                tail += (__bfloat162float(h2.y) + __bfloat162float(l2.y)) * wt[ch + 1];
            }
        }
        out[(size_t)(b * Cn + c) * Tn + t0 + u] = tot + tail;
    }
}

extern "C" void kernel_launch(void* const* d_in, const int* in_sizes, int n_in,
                              void* d_out, int out_size) {
    (void)in_sizes; (void)n_in; (void)out_size;
    const float* coeffs    = (const float*)d_in[0];
    const int*   rows      = (const int*)  d_in[1];
    const int*   cols      = (const int*)  d_in[2];
    const float* ri_scale  = (const float*)d_in[3];
    const float* ri_shift  = (const float*)d_in[4];
    const float* freq_gain = (const float*)d_in[5];
    const float* synth_w   = (const float*)d_in[6];
    float* out = (float*)d_out;

    cudaFuncSetAttribute(wavelet_mma_kernel,
                         cudaFuncAttributeMaxDynamicSharedMemorySize, SMEM_BYTES);
    wavelet_mma_kernel<<<Bn * Cn * 8, NTH, SMEM_BYTES>>>(
        coeffs, rows, cols, ri_scale, ri_shift, freq_gain, synth_w, out);
}